// round 11
// baseline (speedup 1.0000x reference)
#include <cuda_runtime.h>
#include <cuda_fp16.h>

#define BATCH 8
#define SEQ   4096
#define HID   1024
#define K1N   33       // Hermitian: store only k1 = 0..32 of 64
#define P1B   512      // pass1 blocks per batch (8 hblk x 64 n2)
#define P2B   264      // pass2 blocks per batch (8 hblk x 33 k1)
#define PAIR  (P2B + P1B)   // 776
#define NBLK  (BATCH * (P1B + P2B))  // 6208

// Scratch: Y[b][n2][k1(0..32)][h] as half2(re,im): 69 MB total, 8.6 MB/batch.
// With interleaved P1/P2 execution the active batches stay L2-resident.
__device__ __half2 g_scratch[(size_t)BATCH * 64 * K1N * HID];
// Producer->consumer arrival counters, one per batch.
__device__ int g_ready[BATCH];

__global__ void reset_ready() {
    if (threadIdx.x < BATCH) g_ready[threadIdx.x] = 0;
}

// Bit-reverse of 6-bit value (compile-time in unrolled loops)
__device__ __forceinline__ constexpr int rev6(int x) {
    return ((x & 1) << 5) | ((x & 2) << 3) | ((x & 4) << 1) |
           ((x & 8) >> 1) | ((x & 16) >> 3) | ((x & 32) >> 5);
}

// W_64^j, j in [0,32). Literal constants -> FFMA immediates.
__device__ __forceinline__ float tw64_re(int j) {
    constexpr float c[32] = {
        1.00000000000f, 0.99518472667f, 0.98078528040f, 0.95694033573f,
        0.92387953251f, 0.88192126435f, 0.83146961230f, 0.77301045336f,
        0.70710678119f, 0.63439328416f, 0.55557023302f, 0.47139673683f,
        0.38268343236f, 0.29028467725f, 0.19509032202f, 0.09801714033f,
        0.00000000000f,-0.09801714033f,-0.19509032202f,-0.29028467725f,
       -0.38268343236f,-0.47139673683f,-0.55557023302f,-0.63439328416f,
       -0.70710678119f,-0.77301045336f,-0.83146961230f,-0.88192126435f,
       -0.92387953251f,-0.95694033573f,-0.98078528040f,-0.99518472667f };
    return c[j];
}
__device__ __forceinline__ float tw64_im(int j) {
    constexpr float s[32] = {
       -0.00000000000f,-0.09801714033f,-0.19509032202f,-0.29028467725f,
       -0.38268343236f,-0.47139673683f,-0.55557023302f,-0.63439328416f,
       -0.70710678119f,-0.77301045336f,-0.83146961230f,-0.88192126435f,
       -0.92387953251f,-0.95694033573f,-0.98078528040f,-0.99518472667f,
       -1.00000000000f,-0.99518472667f,-0.98078528040f,-0.95694033573f,
       -0.92387953251f,-0.88192126435f,-0.83146961230f,-0.77301045336f,
       -0.70710678119f,-0.63439328416f,-0.55557023302f,-0.47139673683f,
       -0.38268343236f,-0.29028467725f,-0.19509032202f,-0.09801714033f };
    return s[j];
}

// In-register 64-point DIF radix-2 FFT. Output bit-reversed:
// X[k] = re[rev6(k)], im[rev6(k)].
__device__ __forceinline__ void fft64(float (&re)[64], float (&im)[64]) {
#pragma unroll
    for (int stage = 0; stage < 6; stage++) {
        const int s = 32 >> stage;
#pragma unroll
        for (int j = 0; j < 64; j += 2 * s) {
#pragma unroll
            for (int t = 0; t < s; t++) {
                const int a = j + t;
                const int b = a + s;
                float ar = re[a], ai = im[a];
                float br = re[b], bi = im[b];
                re[a] = ar + br;
                im[a] = ai + bi;
                float dr = ar - br, di = ai - bi;
                const int ti = t << stage;
                float wr = tw64_re(ti), wi = tw64_im(ti);
                re[b] = dr * wr - di * wi;
                im[b] = dr * wi + di * wr;
            }
        }
    }
}

// Fused producer/consumer kernel. Block-ID layout (dispatch is in bid order):
//   P1(b0), P1(b1), then for k=0..5: [P2(bk), P1(b_{k+2})], then P2(b6), P2(b7).
// Every P2(b) block has a larger bid than all P1(b) blocks -> P1(b) is always
// dispatched (and running) before any P2(b) can occupy an SM slot: no deadlock.
__global__ void __launch_bounds__(128)
fft_fused(const float* __restrict__ x, float* __restrict__ out) {
    const int bid = blockIdx.x;
    int role, b, sub;
    if (bid < 2 * P1B) {                       // P1 b0, b1
        role = 1; b = bid / P1B; sub = bid % P1B;
    } else {
        const int t = bid - 2 * P1B;
        const int pair = t / PAIR;
        if (pair >= BATCH - 2) {               // tail: P2 b6, b7
            const int tt = t - (BATCH - 2) * PAIR;
            role = 2; b = (BATCH - 2) + tt / P2B; sub = tt % P2B;
        } else {
            const int w = t % PAIR;
            if (w < P2B) { role = 2; b = pair;     sub = w; }
            else         { role = 1; b = pair + 2; sub = w - P2B; }
        }
    }

    if (role == 1) {
        // ---- Pass 1 (R3 body): FFT64 over n1, twiddle, fp16 scratch ----
        const int h  = (sub & 7) * 128 + threadIdx.x;
        const int n2 = sub >> 3;

        const float* xp = x + ((size_t)b * SEQ + n2) * HID + h;
        float re[64], im[64];
#pragma unroll
        for (int n1 = 0; n1 < 64; n1++) {
            re[n1] = __ldcs(xp + (size_t)n1 * 64 * HID);  // streaming read
            im[n1] = 0.0f;
        }
        fft64(re, im);

        float bs, bc;
        sincospif(-(float)n2 / 2048.0f, &bs, &bc);  // W_4096^{n2}

        __half2* yp = g_scratch + ((size_t)(b * 64 + n2) * K1N) * HID + h;
        float wr = 1.0f, wi = 0.0f;
#pragma unroll
        for (int k1 = 0; k1 < K1N; k1++) {
            float vr = re[rev6(k1)], vi = im[rev6(k1)];
            yp[(size_t)k1 * HID] = __floats2half2_rn(vr * wr - vi * wi,
                                                     vr * wi + vi * wr);
            float nwr = wr * bc - wi * bs;
            float nwi = wr * bs + wi * bc;
            wr = nwr; wi = nwi;
        }

        // Release: all stores visible, then arrive.
        __threadfence();
        __syncthreads();
        if (threadIdx.x == 0) atomicAdd(&g_ready[b], 1);
    } else {
        // ---- Pass 2 (R3 body): wait for batch b, FFT64 over n2, write Re ----
        if (threadIdx.x == 0) {
            while (atomicAdd(&g_ready[b], 0) < P1B) __nanosleep(128);
        }
        __syncthreads();
        __threadfence();  // acquire-side ordering before scratch reads

        const int h  = (sub & 7) * 128 + threadIdx.x;
        const int k1 = sub >> 3;                 // 0..32

        const __half2* yp = g_scratch + ((size_t)(b * 64) * K1N + k1) * HID + h;
        float re[64], im[64];
#pragma unroll
        for (int n2 = 0; n2 < 64; n2++) {
            float2 v = __half22float2(yp[(size_t)n2 * K1N * HID]);  // L2 hit
            re[n2] = v.x;
            im[n2] = v.y;
        }
        fft64(re, im);

        float* op = out + ((size_t)b * SEQ) * HID + h;
        const float scale = 1.0f / 64.0f;  // ortho norm 1/sqrt(4096)
#pragma unroll
        for (int k2 = 0; k2 < 64; k2++) {
            __stcs(op + (size_t)(k1 + 64 * k2) * HID, re[rev6(k2)] * scale);
        }
        if (k1 >= 1 && k1 <= 31) {
            const int k1m = 64 - k1;
#pragma unroll
            for (int k2 = 0; k2 < 64; k2++) {
                __stcs(op + (size_t)(k1m + 64 * k2) * HID,
                       re[rev6(63 - k2)] * scale);
            }
        }
    }
}

extern "C" void kernel_launch(void* const* d_in, const int* in_sizes, int n_in,
                              void* d_out, int out_size) {
    const float* x = (const float*)d_in[0];
    float* out = (float*)d_out;

    reset_ready<<<1, 32>>>();
    fft_fused<<<NBLK, 128>>>(x, out);
}

// round 12
// speedup vs baseline: 1.4807x; 1.4807x over previous
#include <cuda_runtime.h>
#include <cuda_fp16.h>

#define BATCH 8
#define SEQ   4096
#define HID   1024
#define K1N   33        // Hermitian: store only k1 = 0..32 of 64
#define NCHUNK 4        // pipeline chunks over batch
#define BPC   (BATCH / NCHUNK)

// Scratch: Y[b][n2][k1(0..32)][h] as half2(re,im): 69 MB total; per-chunk
// working set is 17 MB -> stays L2-resident between P1(c) and P2(c).
__device__ __half2 g_scratch[(size_t)BATCH * 64 * K1N * HID];

// Bit-reverse of 6-bit value (compile-time in unrolled loops)
__device__ __forceinline__ constexpr int rev6(int x) {
    return ((x & 1) << 5) | ((x & 2) << 3) | ((x & 4) << 1) |
           ((x & 8) >> 1) | ((x & 16) >> 3) | ((x & 32) >> 5);
}

// W_64^j, j in [0,32). Literal constants -> FFMA immediates.
__device__ __forceinline__ float tw64_re(int j) {
    constexpr float c[32] = {
        1.00000000000f, 0.99518472667f, 0.98078528040f, 0.95694033573f,
        0.92387953251f, 0.88192126435f, 0.83146961230f, 0.77301045336f,
        0.70710678119f, 0.63439328416f, 0.55557023302f, 0.47139673683f,
        0.38268343236f, 0.29028467725f, 0.19509032202f, 0.09801714033f,
        0.00000000000f,-0.09801714033f,-0.19509032202f,-0.29028467725f,
       -0.38268343236f,-0.47139673683f,-0.55557023302f,-0.63439328416f,
       -0.70710678119f,-0.77301045336f,-0.83146961230f,-0.88192126435f,
       -0.92387953251f,-0.95694033573f,-0.98078528040f,-0.99518472667f };
    return c[j];
}
__device__ __forceinline__ float tw64_im(int j) {
    constexpr float s[32] = {
       -0.00000000000f,-0.09801714033f,-0.19509032202f,-0.29028467725f,
       -0.38268343236f,-0.47139673683f,-0.55557023302f,-0.63439328416f,
       -0.70710678119f,-0.77301045336f,-0.83146961230f,-0.88192126435f,
       -0.92387953251f,-0.95694033573f,-0.98078528040f,-0.99518472667f,
       -1.00000000000f,-0.99518472667f,-0.98078528040f,-0.95694033573f,
       -0.92387953251f,-0.88192126435f,-0.83146961230f,-0.77301045336f,
       -0.70710678119f,-0.63439328416f,-0.55557023302f,-0.47139673683f,
       -0.38268343236f,-0.29028467725f,-0.19509032202f,-0.09801714033f };
    return s[j];
}

// In-register 64-point DIF radix-2 FFT. Output bit-reversed:
// X[k] = re[rev6(k)], im[rev6(k)].
__device__ __forceinline__ void fft64(float (&re)[64], float (&im)[64]) {
#pragma unroll
    for (int stage = 0; stage < 6; stage++) {
        const int s = 32 >> stage;
#pragma unroll
        for (int j = 0; j < 64; j += 2 * s) {
#pragma unroll
            for (int t = 0; t < s; t++) {
                const int a = j + t;
                const int b = a + s;
                float ar = re[a], ai = im[a];
                float br = re[b], bi = im[b];
                re[a] = ar + br;
                im[a] = ai + bi;
                float dr = ar - br, di = ai - bi;
                const int ti = t << stage;
                float wr = tw64_re(ti), wi = tw64_im(ti);
                re[b] = dr * wr - di * wi;
                im[b] = dr * wi + di * wr;
            }
        }
    }
}

// Pass 1 (R3 body + batch offset): per (b, n2, h):
// A[k1] = FFT64 over n1; Y = A[k1] * W_4096^{n2*k1}, fp16, k1 = 0..32.
__global__ void __launch_bounds__(128) fft_pass1(const float* __restrict__ x,
                                                 int b0) {
    const int h  = blockIdx.x * 128 + threadIdx.x;  // HID/128 = 8
    const int n2 = blockIdx.y;                      // 64
    const int b  = b0 + blockIdx.z;

    const float* xp = x + ((size_t)b * SEQ + n2) * HID + h;
    float re[64], im[64];
#pragma unroll
    for (int n1 = 0; n1 < 64; n1++) {
        re[n1] = __ldcs(xp + (size_t)n1 * 64 * HID);  // streaming read
        im[n1] = 0.0f;
    }
    fft64(re, im);

    // base twiddle W_4096^{n2} = exp(-i*pi*n2/2048)
    float bs, bc;
    sincospif(-(float)n2 / 2048.0f, &bs, &bc);

    __half2* yp = g_scratch + ((size_t)(b * 64 + n2) * K1N) * HID + h;
    float wr = 1.0f, wi = 0.0f;  // W^0
#pragma unroll
    for (int k1 = 0; k1 < K1N; k1++) {
        float vr = re[rev6(k1)], vi = im[rev6(k1)];
        yp[(size_t)k1 * HID] = __floats2half2_rn(vr * wr - vi * wi,
                                                 vr * wi + vi * wr);
        float nwr = wr * bc - wi * bs;
        float nwi = wr * bs + wi * bc;
        wr = nwr; wi = nwi;
    }
}

// Pass 2 (R3 body + batch offset): per (b, k1, h):
// X[k1 + 64*k2] = FFT64 over n2 of Y[n2][k1]; write Re*(1/64) + mirror row.
__global__ void __launch_bounds__(128) fft_pass2(float* __restrict__ out,
                                                 int b0) {
    const int h  = blockIdx.x * 128 + threadIdx.x;
    const int k1 = blockIdx.y;                      // 0..32
    const int b  = b0 + blockIdx.z;

    const __half2* yp = g_scratch + ((size_t)(b * 64) * K1N + k1) * HID + h;
    float re[64], im[64];
#pragma unroll
    for (int n2 = 0; n2 < 64; n2++) {
        float2 v = __half22float2(yp[(size_t)n2 * K1N * HID]);  // L2 hit
        re[n2] = v.x;
        im[n2] = v.y;
    }
    fft64(re, im);

    float* op = out + ((size_t)b * SEQ) * HID + h;
    const float scale = 1.0f / 64.0f;  // ortho norm 1/sqrt(4096)
#pragma unroll
    for (int k2 = 0; k2 < 64; k2++) {
        __stcs(op + (size_t)(k1 + 64 * k2) * HID, re[rev6(k2)] * scale);
    }
    if (k1 >= 1 && k1 <= 31) {
        const int k1m = 64 - k1;
#pragma unroll
        for (int k2 = 0; k2 < 64; k2++) {
            __stcs(op + (size_t)(k1m + 64 * k2) * HID, re[rev6(63 - k2)] * scale);
        }
    }
}

extern "C" void kernel_launch(void* const* d_in, const int* in_sizes, int n_in,
                              void* d_out, int out_size) {
    const float* x = (const float*)d_in[0];
    float* out = (float*)d_out;

    // One-time setup on the first (correctness) call; nothing created during
    // capture. No device memory is allocated. Both pipeline stages run on
    // explicit non-blocking streams -- the legacy default stream's implicit
    // global sync (which serialized R7's pipeline) never touches them.
    static cudaStream_t s1 = nullptr, s2 = nullptr;
    static cudaEvent_t evRoot = nullptr, evP1[NCHUNK], evDone = nullptr;
    if (s1 == nullptr) {
        cudaStreamCreateWithFlags(&s1, cudaStreamNonBlocking);
        cudaStreamCreateWithFlags(&s2, cudaStreamNonBlocking);
        cudaEventCreateWithFlags(&evRoot, cudaEventDisableTiming);
        for (int c = 0; c < NCHUNK; c++)
            cudaEventCreateWithFlags(&evP1[c], cudaEventDisableTiming);
        cudaEventCreateWithFlags(&evDone, cudaEventDisableTiming);
    }

    // Fork both streams from the caller's stream (joins them into capture).
    cudaEventRecord(evRoot, 0);
    cudaStreamWaitEvent(s1, evRoot, 0);

    // Pipeline: P1 chain on s1; P2(c) on s2 waits only on P1(c) (+ P2(c-1)).
    // P1(c+1) runs concurrently with P2(c): reads overlap writes on the bus.
    for (int c = 0; c < NCHUNK; c++) {
        fft_pass1<<<dim3(HID / 128, 64, BPC), 128, 0, s1>>>(x, c * BPC);
        cudaEventRecord(evP1[c], s1);
        cudaStreamWaitEvent(s2, evP1[c], 0);
        fft_pass2<<<dim3(HID / 128, K1N, BPC), 128, 0, s2>>>(out, c * BPC);
    }
    // Join back to the caller's stream. s2's completion implies s1's
    // (P2(last) waits on P1(last) via evP1[last]).
    cudaEventRecord(evDone, s2);
    cudaStreamWaitEvent(0, evDone, 0);
}